// round 11
// baseline (speedup 1.0000x reference)
#include <cuda_runtime.h>
#include <cuda_bf16.h>
#include <cstdint>

#define M_TOT 65536
#define START_TAG 30
#define NEGV  (-10000.0f)

// ---------------- device scratch ----------------
__device__ __nv_bfloat16 g_xemb[(size_t)M_TOT * 256];
__device__ __nv_bfloat16 g_wih[2 * 1024 * 256];
__device__ __nv_bfloat16 g_whh[2 * 1024 * 256];
__device__ __nv_bfloat16 g_wo[32 * 512];
__device__ float g_bias[2 * 1024];
__device__ float g_etrans[32 * 32];
__device__ __nv_bfloat16 g_h[(size_t)M_TOT * 512];
__device__ float g_feats[(size_t)M_TOT * 32];
__device__ float g_Z[128];
__device__ float g_gold[128];

// ---------------- helpers ----------------
__device__ __forceinline__ unsigned sptr(const void* p) {
    return (unsigned)__cvta_generic_to_shared(p);
}
__device__ __forceinline__ void ldsm4(unsigned* r, unsigned addr) {
    asm volatile("ldmatrix.sync.aligned.m8n8.x4.shared.b16 {%0,%1,%2,%3},[%4];"
                 : "=r"(r[0]), "=r"(r[1]), "=r"(r[2]), "=r"(r[3]) : "r"(addr));
}
__device__ __forceinline__ void ldsm4t(unsigned* r, unsigned addr) {
    asm volatile("ldmatrix.sync.aligned.m8n8.x4.trans.shared.b16 {%0,%1,%2,%3},[%4];"
                 : "=r"(r[0]), "=r"(r[1]), "=r"(r[2]), "=r"(r[3]) : "r"(addr));
}
__device__ __forceinline__ void mma16816(float* d, const unsigned* a, const unsigned* b) {
    asm volatile("mma.sync.aligned.m16n8k16.row.col.f32.bf16.bf16.f32 "
                 "{%0,%1,%2,%3},{%4,%5,%6,%7},{%8,%9},{%0,%1,%2,%3};"
                 : "+f"(d[0]), "+f"(d[1]), "+f"(d[2]), "+f"(d[3])
                 : "r"(a[0]), "r"(a[1]), "r"(a[2]), "r"(a[3]), "r"(b[0]), "r"(b[1]));
}
__device__ __forceinline__ unsigned packbf(float a, float b) {
    __nv_bfloat162 t = __float22bfloat162_rn(make_float2(a, b));
    return *(unsigned*)&t;
}
__device__ __forceinline__ float tanha(float x) {
    float y; asm("tanh.approx.f32 %0, %1;" : "=f"(y) : "f"(x)); return y;
}
__device__ __forceinline__ float sigax(float x) {
    return fmaf(tanha(x * 0.5f), 0.5f, 0.5f);
}
__device__ __forceinline__ void mbar_wait(unsigned mbar, int parity) {
    asm volatile(
        "{\n\t.reg .pred P;\n"
        "WL_%=:\n\t"
        "mbarrier.try_wait.parity.acquire.cluster.shared::cta.b64 P, [%0], %1, 0x989680;\n\t"
        "@P bra.uni WD_%=;\n\t"
        "bra.uni WL_%=;\n"
        "WD_%=:\n\t}"
        :: "r"(mbar), "r"(parity) : "memory");
}

// ---------------- prep ----------------
// gate-local permutation: stored row n' decomposes as
//   jt = n'>>7, w = (n'>>4)&7, p = n'&15, e = p>>3, d = p&1, q = (p>>1)&3
// and maps to original W row  (d + 2e)*256 + jt*32 + w*4 + q
// so the mma fragment of one lane holds the 4 gates (i,f,g,o) of one cell.
__global__ void prep_misc(const float* __restrict__ Wf, const float* __restrict__ Whf,
                          const float* __restrict__ bf, const float* __restrict__ Wb,
                          const float* __restrict__ Whb, const float* __restrict__ bb,
                          const float* __restrict__ Wo, const float* __restrict__ trans)
{
    int idx = blockIdx.x * blockDim.x + threadIdx.x;
    int stride = gridDim.x * blockDim.x;
    for (int i = idx; i < 2 * 1024 * 256; i += stride) {
        int dir = i >> 18;
        int r = (i >> 8) & 1023;
        int k = i & 255;
        int jt = r >> 7, w = (r >> 4) & 7, p = r & 15;
        int e = p >> 3, d = p & 1, q = (p >> 1) & 3;
        int pr = (d + 2 * e) * 256 + jt * 32 + w * 4 + q;
        const float* Wi = dir ? Wb : Wf;
        const float* Wh = dir ? Whb : Whf;
        g_wih[i] = __float2bfloat16(Wi[pr * 256 + k]);
        g_whh[i] = __float2bfloat16(Wh[pr * 256 + k]);
    }
    for (int i = idx; i < 32 * 512; i += stride) g_wo[i] = __float2bfloat16(Wo[i]);
    for (int i = idx; i < 2048; i += stride) {
        int dir = i >> 10;
        int r = i & 1023;
        int jt = r >> 7, w = (r >> 4) & 7, p = r & 15;
        int e = p >> 3, d = p & 1, q = (p >> 1) & 3;
        int pr = (d + 2 * e) * 256 + jt * 32 + w * 4 + q;
        g_bias[i] = (dir ? bb : bf)[pr];
    }
    for (int i = idx; i < 1024; i += stride) g_etrans[i] = __expf(trans[i]);
}

// ---------------- gather emb[sent] -> bf16 ----------------
__global__ void __launch_bounds__(256) gather_k(const float* __restrict__ emb,
                                                const int* __restrict__ sent)
{
    int m = blockIdx.x * 8 + (threadIdx.x >> 5);
    int lane = threadIdx.x & 31;
    int tok = sent[m];
    const float4* src = (const float4*)(emb + (size_t)tok * 256) + lane * 2;
    float4 a = src[0], b = src[1];
    uint4 v = make_uint4(packbf(a.x, a.y), packbf(a.z, a.w),
                         packbf(b.x, b.y), packbf(b.z, b.w));
    *(uint4*)(g_xemb + (size_t)m * 256 + lane * 8) = v;
}

// ---------------- persistent bi-LSTM: cluster of 8, bulk DSMEM + mbarrier ----------------
#define SX_ELEM (16 * 264)
#define SX_BYTES (SX_ELEM * 2)

__device__ __forceinline__ void cp_x_tile(unsigned sbase, const __nv_bfloat16* g, int tx) {
    const int row = tx >> 4, seg = tx & 15;
    unsigned sa = sbase + (unsigned)((row * 264 + seg * 16) << 1);
    const __nv_bfloat16* ga = g + (size_t)row * 256 + seg * 16;
    asm volatile("cp.async.cg.shared.global [%0],[%1],16;" :: "r"(sa), "l"(ga));
    asm volatile("cp.async.cg.shared.global [%0],[%1],16;" :: "r"(sa + 16), "l"(ga + 8));
    asm volatile("cp.async.commit_group;");
}

__global__ void __launch_bounds__(256, 1) __cluster_dims__(8, 1, 1)
lstm_k(const float* __restrict__ h0, const float* __restrict__ c0)
{
    __shared__ __align__(16) __nv_bfloat16 sAB[2][4096];    // 2 x 8KB receive buffers
    __shared__ __align__(16) __nv_bfloat16 sX[2][SX_ELEM];
    __shared__ __align__(16) __nv_bfloat16 sStage[2][512];  // my 1KB block (for peers)
    __shared__ __align__(8) unsigned long long mbars[2];
    const int tx = threadIdx.x, w = tx >> 5, lane = tx & 31;
    const int bx = blockIdx.x;
    const int dir = bx >> 6, cid = bx & 63;
    const int b0 = (cid >> 3) << 4;
    const int jt = bx & 7;             // cluster rank
    const int N0 = jt << 7;
    const int j0 = jt << 5;

    // --- W_hh / W_ih fragments in registers ---
    unsigned bw[16][2][2], bwi[16][2][2];
    {
        const int row = N0 + w * 16 + (lane >> 2);
        const __nv_bfloat16* baseH = g_whh + (size_t)dir * 1024 * 256;
        const __nv_bfloat16* baseI = g_wih + (size_t)dir * 1024 * 256;
#pragma unroll
        for (int kf = 0; kf < 16; kf++) {
#pragma unroll
            for (int nf = 0; nf < 2; nf++) {
                const size_t off = (size_t)(row + nf * 8) * 256 + kf * 16 + (lane & 3) * 2;
                bw[kf][nf][0]  = *(const unsigned*)(baseH + off);
                bw[kf][nf][1]  = *(const unsigned*)(baseH + off + 8);
                bwi[kf][nf][0] = *(const unsigned*)(baseI + off);
                bwi[kf][nf][1] = *(const unsigned*)(baseI + off + 8);
            }
        }
    }

    const int r = lane >> 2;           // row 0..7 (and r+8)
    const int q = lane & 3;            // my cell within warp group
    const int jc = w * 4 + q;          // cell 0..31 of this j-tile
    const int xcol = N0 + w * 16 + q * 2;

    float bb0[2], bb1[2];
#pragma unroll
    for (int nf = 0; nf < 2; nf++) {
        bb0[nf] = g_bias[dir * 1024 + xcol + nf * 8];
        bb1[nf] = g_bias[dir * 1024 + xcol + nf * 8 + 1];
    }

    float cs[2];
#pragma unroll
    for (int h2 = 0; h2 < 2; h2++)
        cs[h2] = c0[(size_t)(dir * 128 + b0 + r + h2 * 8) * 256 + j0 + jc];

    // --- mbarrier init + arm phase 0 (expect 7 x 1KB from peers) ---
    if (tx == 0) {
#pragma unroll
        for (int i = 0; i < 2; i++) {
            unsigned mb = sptr(&mbars[i]);
            asm volatile("mbarrier.init.shared.b64 [%0], 1;" :: "r"(mb) : "memory");
            asm volatile("mbarrier.arrive.expect_tx.shared.b64 _, [%0], 7168;" :: "r"(mb) : "memory");
        }
    }

    // --- init sAB[0] from h0 (block k-major swizzled layout) ---
    for (int i = tx; i < 4096; i += 256) {
        const int k = i >> 4, m = i & 15;
        const int rank = k >> 5, kk = k & 31;
        const int eoff = rank * 512 + kk * 16 + (((m >> 3) ^ ((kk >> 2) & 1)) << 3) + (m & 7);
        sAB[0][eoff] = __float2bfloat16(h0[(size_t)(dir * 128 + b0 + m) * 256 + k]);
    }

    // --- peer addresses ---
    unsigned psa[8], pmb[8];
    {
        unsigned la = sptr(&sAB[0][0]);
        unsigned lm = sptr(&mbars[0]);
#pragma unroll
        for (int p = 0; p < 8; p++) {
            asm("mapa.shared::cluster.u32 %0, %1, %2;" : "=r"(psa[p]) : "r"(la), "r"(p));
            asm("mapa.shared::cluster.u32 %0, %1, %2;" : "=r"(pmb[p]) : "r"(lm), "r"(p));
        }
    }

    // --- ldmatrix.trans lane addressing for h blocks ---
    const int g = lane >> 3, lsub = lane & 7;
    const int kbase = lsub + ((g >> 1) << 3);
    const unsigned aoffH =
        (unsigned)(kbase * 32 + (((g & 1) ^ ((kbase >> 2) & 1)) << 4));
    const unsigned hBase = sptr(&sAB[0][0]);
    const unsigned aX0 = sptr(&sX[0][0]) + (((lane & 15) * 264 + (lane >> 4) * 8) << 1);

    // --- prologue: emb t0 -> sX[1], t1 -> sX[0] ---
    cp_x_tile(sptr(&sX[0][0]) + SX_BYTES,
              g_xemb + (size_t)((dir ? 511 : 0) * 128 + b0) * 256, tx);
    cp_x_tile(sptr(&sX[0][0]),
              g_xemb + (size_t)((dir ? 510 : 1) * 128 + b0) * 256, tx);
    asm volatile("cp.async.wait_group 1;");
    __syncthreads();

    asm volatile("barrier.cluster.arrive.aligned;" ::: "memory");

    // --- prologue x-projection (t0) ---
    float xacc[2][4];
    {
        float a0[2][4], a1[2][4];
#pragma unroll
        for (int nf = 0; nf < 2; nf++) {
            a0[nf][0] = bb0[nf]; a0[nf][1] = bb1[nf];
            a0[nf][2] = bb0[nf]; a0[nf][3] = bb1[nf];
            a1[nf][0] = a1[nf][1] = a1[nf][2] = a1[nf][3] = 0.0f;
        }
        const unsigned aX = aX0 + SX_BYTES;
#pragma unroll
        for (int kf = 0; kf < 16; kf += 2) {
            unsigned af[4], af2[4];
            ldsm4(af, aX + kf * 32);
            mma16816(a0[0], af, bwi[kf][0]);
            mma16816(a0[1], af, bwi[kf][1]);
            ldsm4(af2, aX + kf * 32 + 32);
            mma16816(a1[0], af2, bwi[kf + 1][0]);
            mma16816(a1[1], af2, bwi[kf + 1][1]);
        }
#pragma unroll
        for (int nf = 0; nf < 2; nf++)
#pragma unroll
            for (int i = 0; i < 4; i++) xacc[nf][i] = a0[nf][i] + a1[nf][i];
    }
    asm volatile("barrier.cluster.wait.aligned;" ::: "memory");

    int ph[2] = {0, 0};

    for (int s = 0; s < 512; s++) {
        const int t = dir ? (511 - s) : s;
        const int cur = s & 1, nxt = cur ^ 1;

        if (s > 0) {
            const unsigned mb = sptr(&mbars[cur]);
            mbar_wait(mb, ph[cur]);
            ph[cur] ^= 1;
            if (tx == 0 && s < 510)
                asm volatile("mbarrier.arrive.expect_tx.shared.b64 _, [%0], 7168;"
                             :: "r"(mb) : "memory");
        }

        // --- h-mma from sAB[cur] ---
        float acc0[2][4], acc1[2][4];
#pragma unroll
        for (int nf = 0; nf < 2; nf++)
#pragma unroll
            for (int i = 0; i < 4; i++) { acc0[nf][i] = 0.0f; acc1[nf][i] = 0.0f; }

        const unsigned hA = hBase + (unsigned)cur * 8192 + aoffH;
#pragma unroll
        for (int kf = 0; kf < 16; kf += 2) {
            unsigned af[4], af2[4];
            ldsm4t(af, hA + (kf >> 1) * 1024);
            mma16816(acc0[0], af, bw[kf][0]);
            mma16816(acc0[1], af, bw[kf][1]);
            ldsm4t(af2, hA + (kf >> 1) * 1024 + 512);
            mma16816(acc1[0], af2, bw[kf + 1][0]);
            mma16816(acc1[1], af2, bw[kf + 1][1]);
        }

        // --- gates: fully lane-local (i,f at nf=0 cols; g,o at nf=1 cols) ---
        float hv[2];
#pragma unroll
        for (int h2 = 0; h2 < 2; h2++) {
            float pi = acc0[0][h2 * 2 + 0] + acc1[0][h2 * 2 + 0] + xacc[0][h2 * 2 + 0];
            float pf = acc0[0][h2 * 2 + 1] + acc1[0][h2 * 2 + 1] + xacc[0][h2 * 2 + 1];
            float pg = acc0[1][h2 * 2 + 0] + acc1[1][h2 * 2 + 0] + xacc[1][h2 * 2 + 0];
            float po = acc0[1][h2 * 2 + 1] + acc1[1][h2 * 2 + 1] + xacc[1][h2 * 2 + 1];
            float ig = sigax(pi), fg = sigax(pf);
            float gg = tanha(pg), og = sigax(po);
            float c = fmaf(fg, cs[h2], ig * gg);
            cs[h2] = c;
            hv[h2] = og * tanha(c);
        }

        // --- stage into sStage[nxt] (for peers) and own sAB[nxt] block ---
        if (s < 511) {
            __nv_bfloat16 b0v = __float2bfloat16_rn(hv[0]);
            __nv_bfloat16 b1v = __float2bfloat16_rn(hv[1]);
            const int e0 = jc * 16 + ((0 ^ ((jc >> 2) & 1)) << 3) + r;
            const int e1 = jc * 16 + ((1 ^ ((jc >> 2) & 1)) << 3) + r;
            sStage[nxt][e0] = b0v;
            sStage[nxt][e1] = b1v;
            sAB[nxt][jt * 512 + e0] = b0v;
            sAB[nxt][jt * 512 + e1] = b1v;
        }

        __syncthreads();   // staging complete

        // --- elected thread: 7 bulk copies into peers' sAB[nxt] ---
        if (s < 511 && tx == 0) {
            asm volatile("fence.proxy.async.shared::cta;" ::: "memory");
            const unsigned src = sptr(&sStage[nxt][0]);
            const unsigned dstoff = (unsigned)(nxt * 8192 + jt * 1024);
            const unsigned mboff = (unsigned)(nxt * 8);
#pragma unroll
            for (int p = 0; p < 8; p++) {
                if (p == jt) continue;
                asm volatile(
                    "cp.async.bulk.shared::cluster.shared::cta.mbarrier::complete_tx::bytes "
                    "[%0], [%1], 1024, [%2];"
                    :: "r"(psa[p] + dstoff), "r"(src), "r"(pmb[p] + mboff) : "memory");
            }
        }

        // --- prefetch emb tile for t+2 ---
        if (s < 510) {
            const int t2 = dir ? (509 - s) : (s + 2);
            cp_x_tile(sptr(&sX[0][0]) + (unsigned)(nxt * SX_BYTES),
                      g_xemb + (size_t)(t2 * 128 + b0) * 256, tx);
        }

        // --- g_h global write (per-lane bf16, row-coalesced across quads) ---
        g_h[(size_t)(t * 128 + b0 + r) * 512 + dir * 256 + j0 + jc] = __float2bfloat16_rn(hv[0]);
        g_h[(size_t)(t * 128 + b0 + r + 8) * 512 + dir * 256 + j0 + jc] = __float2bfloat16_rn(hv[1]);

        // --- x-projection for step s+1 (overlaps fabric drain) ---
        if (s < 511) {
            if (s < 510) asm volatile("cp.async.wait_group 1;");
            else         asm volatile("cp.async.wait_group 0;");
            __syncthreads();

            float a0[2][4], a1[2][4];
#pragma unroll
            for (int nf = 0; nf < 2; nf++) {
                a0[nf][0] = bb0[nf]; a0[nf][1] = bb1[nf];
                a0[nf][2] = bb0[nf]; a0[nf][3] = bb1[nf];
                a1[nf][0] = a1[nf][1] = a1[nf][2] = a1[nf][3] = 0.0f;
            }
            const unsigned aX = aX0 + (unsigned)cur * SX_BYTES;
#pragma unroll
            for (int kf = 0; kf < 16; kf += 2) {
                unsigned af[4], af2[4];
                ldsm4(af, aX + kf * 32);
                mma16816(a0[0], af, bwi[kf][0]);
                mma16816(a0[1], af, bwi[kf][1]);
                ldsm4(af2, aX + kf * 32 + 32);
                mma16816(a1[0], af2, bwi[kf + 1][0]);
                mma16816(a1[1], af2, bwi[kf + 1][1]);
            }
#pragma unroll
            for (int nf = 0; nf < 2; nf++)
#pragma unroll
                for (int i = 0; i < 4; i++) xacc[nf][i] = a0[nf][i] + a1[nf][i];
        }
    }

    asm volatile("barrier.cluster.arrive.aligned;" ::: "memory");
    asm volatile("barrier.cluster.wait.aligned;" ::: "memory");
}

// ---------------- feats = g_h @ Wo^T + bo  (bf16 mma) ----------------
#define FAS 40
__global__ void __launch_bounds__(256) feats_k(const float* __restrict__ bo)
{
    __shared__ __nv_bfloat16 sB[32 * 520];
    __shared__ __nv_bfloat16 sA[128 * FAS];
    const int tx = threadIdx.x, w = tx >> 5, lane = tx & 31;
    const size_t m0 = (size_t)blockIdx.x * 128;
    const int moff = w * 16;

    for (int i = tx * 8; i < 16384; i += 2048) {
        int row = i >> 9, k = i & 511;
        *(uint4*)&sB[row * 520 + k] = *(const uint4*)&g_wo[i];
    }

    float acc[4][4];
#pragma unroll
    for (int a = 0; a < 4; a++)
#pragma unroll
        for (int b = 0; b < 4; b++) acc[a][b] = 0.0f;

    const int lrow = tx >> 2, lcol = (tx & 3) * 8;
    const __nv_bfloat16* gA = g_h + (m0 + lrow) * 512 + lcol;
    uint4 ra[2];
    ra[0] = *(const uint4*)(gA);
    ra[1] = *(const uint4*)(gA + 64 * 512);

    const unsigned aAddrBase = sptr(sA) + (((moff + (lane & 15)) * FAS + (lane >> 4) * 8) << 1);
    const int bg = lane >> 3;
    const unsigned bAddrBase = sptr(sB) + ((((bg >> 1) * 8 + (lane & 7)) * 520 + (bg & 1) * 8) << 1);

    for (int kc = 0; kc < 16; kc++) {
        __syncthreads();
        *(uint4*)&sA[lrow * FAS + lcol] = ra[0];
        *(uint4*)&sA[(lrow + 64) * FAS + lcol] = ra[1];
        __syncthreads();
        if (kc < 15) {
            ra[0] = *(const uint4*)(gA + (kc + 1) * 32);
            ra[1] = *(const uint4*)(gA + 64 * 512 + (kc + 1) * 32);
        }
#pragma unroll
        for (int kf = 0; kf < 2; kf++) {
            unsigned af[4];
            ldsm4(af, aAddrBase + kf * 32);
#pragma unroll
            for (int p = 0; p < 2; p++) {
                unsigned b4[4];
                ldsm4(b4, bAddrBase + (p * 16 * 520 * 2) + kc * 64 + kf * 32);
                mma16816(acc[2 * p + 0], af, &b4[0]);
                mma16816(acc[2 * p + 1], af, &b4[2]);
            }
        }
    }

#pragma unroll
    for (int nf = 0; nf < 4; nf++) {
        const int l = nf * 8 + (lane & 3) * 2;
        const float b0v = bo[l], b1v = bo[l + 1];
        const size_t mlo = m0 + moff + (lane >> 2);
        float2 v0 = make_float2(acc[nf][0] + b0v, acc[nf][1] + b1v);
        float2 v1 = make_float2(acc[nf][2] + b0v, acc[nf][3] + b1v);
        *(float2*)&g_feats[mlo * 32 + l] = v0;
        *(float2*)&g_feats[(mlo + 8) * 32 + l] = v1;
    }
}

// ---------------- CRF forward: linear-space, lane0-rescale, analytic first step ----------------
__global__ void __launch_bounds__(32) crf_fwd_kernel(const float* __restrict__ trans)
{
    const int b = blockIdx.x;
    const int l = threadIdx.x;

    float er[32];
#pragma unroll
    for (int i = 0; i < 32; i++) er[i] = g_etrans[i * 32 + l];

    // step 0 analytically: dp0 is NEG everywhere except START=0
    float dp = trans[START_TAG * 32 + l] + g_feats[(size_t)(0 * 128 + b) * 32 + l];
    float sc_next = g_feats[(size_t)(1 * 128 + b) * 32 + l];

    for (int t = 1; t < 512; t++) {
        float sc = sc_next;
        if (t < 511) sc_next = g_feats[(size_t)((t + 1) * 128 + b) * 32 + l];
        float m = __shfl_sync(0xffffffffu, dp, 0);   // rescale point (spread bounded)
        float u = __expf(dp - m);
        float a0 = 0.0f, a1 = 0.0f, a2 = 0.0f, a3 = 0.0f;
#pragma unroll
        for (int i = 0; i < 8; i++) {
            a0 = fmaf(__shfl_sync(0xffffffffu, u, i), er[i], a0);
            a1 = fmaf(__shfl_sync(0xffffffffu, u, i + 8), er[i + 8], a1);
            a2 = fmaf(__shfl_sync(0xffffffffu, u, i + 16), er[i + 16], a2);
            a3 = fmaf(__shfl_sync(0xffffffffu, u, i + 24), er[i + 24], a3);
        }
        dp = m + __logf((a0 + a1) + (a2 + a3)) + sc;
    }

    float m = dp;
#pragma unroll
    for (int o = 16; o; o >>= 1) m = fmaxf(m, __shfl_xor_sync(0xffffffffu, m, o));
    float e = __expf(dp - m);
#pragma unroll
    for (int o = 16; o; o >>= 1) e += __shfl_xor_sync(0xffffffffu, e, o);
    if (l == 0) g_Z[b] = m + __logf(e);
}

// ---------------- gold path score ----------------
__global__ void __launch_bounds__(256) gold_k(const int* __restrict__ labels,
                                              const float* __restrict__ trans)
{
    __shared__ float red[256];
    const int b = blockIdx.x, tx = threadIdx.x;
    float s = 0.0f;
    for (int t = tx; t < 512; t += 256) {
        int ln = labels[t * 128 + b];
        int lp = t ? labels[(t - 1) * 128 + b] : START_TAG;
        s += trans[lp * 32 + ln] + g_feats[(size_t)(t * 128 + b) * 32 + ln];
    }
    red[tx] = s;
    __syncthreads();
    for (int o = 128; o; o >>= 1) {
        if (tx < o) red[tx] += red[tx + o];
        __syncthreads();
    }
    if (tx == 0) g_gold[b] = red[0];
}

// ---------------- final reduce ----------------
__global__ void __launch_bounds__(128) final_kernel(float* __restrict__ out)
{
    __shared__ float red[128];
    const int b = threadIdx.x;
    red[b] = g_Z[b] - g_gold[b];
    __syncthreads();
    for (int o = 64; o; o >>= 1) {
        if (b < o) red[b] += red[b + o];
        __syncthreads();
    }
    if (b == 0) out[0] = red[0] / 128.0f;
}

// ---------------- launch ----------------
extern "C" void kernel_launch(void* const* d_in, const int* in_sizes, int n_in,
                              void* d_out, int out_size)
{
    (void)in_sizes; (void)n_in; (void)out_size;
    const float* emb    = (const float*)d_in[0];
    const float* W_ih_f = (const float*)d_in[1];
    const float* W_hh_f = (const float*)d_in[2];
    const float* b_f    = (const float*)d_in[3];
    const float* W_ih_b = (const float*)d_in[4];
    const float* W_hh_b = (const float*)d_in[5];
    const float* b_b    = (const float*)d_in[6];
    const float* Wo     = (const float*)d_in[7];
    const float* bo     = (const float*)d_in[8];
    const float* trans  = (const float*)d_in[9];
    const float* h0     = (const float*)d_in[10];
    const float* c0     = (const float*)d_in[11];
    const int*   sent   = (const int*)d_in[12];
    const int*   labels = (const int*)d_in[13];
    float* out = (float*)d_out;

    prep_misc<<<512, 256>>>(W_ih_f, W_hh_f, b_f, W_ih_b, W_hh_b, b_b, Wo, trans);
    gather_k<<<8192, 256>>>(emb, sent);
    lstm_k<<<128, 256>>>(h0, c0);
    feats_k<<<512, 256>>>(bo);
    crf_fwd_kernel<<<128, 32>>>(trans);
    gold_k<<<128, 256>>>(labels, trans);
    final_kernel<<<1, 128>>>(out);
}

// round 13
// speedup vs baseline: 2.1843x; 2.1843x over previous
#include <cuda_runtime.h>
#include <cuda_bf16.h>
#include <cstdint>

#define M_TOT 65536
#define START_TAG 30
#define NEGV  (-10000.0f)

// ---------------- device scratch ----------------
__device__ __nv_bfloat16 g_xemb[(size_t)M_TOT * 256];
__device__ __nv_bfloat16 g_wih[2 * 1024 * 256];
__device__ __nv_bfloat16 g_whh[2 * 1024 * 256];
__device__ __nv_bfloat16 g_wo[32 * 512];
__device__ float g_bias[2 * 1024];
__device__ float g_etrans[32 * 32];
__device__ __nv_bfloat16 g_x[(size_t)2 * M_TOT * 1024];   // proj output (bias folded in)
__device__ __nv_bfloat16 g_h[(size_t)M_TOT * 512];
__device__ float g_feats[(size_t)M_TOT * 32];
__device__ float g_Z[128];
__device__ float g_gold[128];

// ---------------- helpers ----------------
__device__ __forceinline__ unsigned sptr(const void* p) {
    return (unsigned)__cvta_generic_to_shared(p);
}
__device__ __forceinline__ void ldsm4(unsigned* r, unsigned addr) {
    asm volatile("ldmatrix.sync.aligned.m8n8.x4.shared.b16 {%0,%1,%2,%3},[%4];"
                 : "=r"(r[0]), "=r"(r[1]), "=r"(r[2]), "=r"(r[3]) : "r"(addr));
}
__device__ __forceinline__ void ldsm4t(unsigned* r, unsigned addr) {
    asm volatile("ldmatrix.sync.aligned.m8n8.x4.trans.shared.b16 {%0,%1,%2,%3},[%4];"
                 : "=r"(r[0]), "=r"(r[1]), "=r"(r[2]), "=r"(r[3]) : "r"(addr));
}
__device__ __forceinline__ void mma16816(float* d, const unsigned* a, const unsigned* b) {
    asm volatile("mma.sync.aligned.m16n8k16.row.col.f32.bf16.bf16.f32 "
                 "{%0,%1,%2,%3},{%4,%5,%6,%7},{%8,%9},{%0,%1,%2,%3};"
                 : "+f"(d[0]), "+f"(d[1]), "+f"(d[2]), "+f"(d[3])
                 : "r"(a[0]), "r"(a[1]), "r"(a[2]), "r"(a[3]), "r"(b[0]), "r"(b[1]));
}
__device__ __forceinline__ unsigned packbf(float a, float b) {
    __nv_bfloat162 t = __float22bfloat162_rn(make_float2(a, b));
    return *(unsigned*)&t;
}
__device__ __forceinline__ float lo16(unsigned u) { return __uint_as_float(u << 16); }
__device__ __forceinline__ float hi16(unsigned u) { return __uint_as_float(u & 0xffff0000u); }
__device__ __forceinline__ float tanha(float x) {
    float y; asm("tanh.approx.f32 %0, %1;" : "=f"(y) : "f"(x)); return y;
}
__device__ __forceinline__ float sigax(float x) {
    return fmaf(tanha(x * 0.5f), 0.5f, 0.5f);
}
__device__ __forceinline__ void mbar_wait(unsigned mbar, int parity) {
    asm volatile(
        "{\n\t.reg .pred P;\n"
        "WL_%=:\n\t"
        "mbarrier.try_wait.parity.acquire.cluster.shared::cta.b64 P, [%0], %1, 0x989680;\n\t"
        "@P bra.uni WD_%=;\n\t"
        "bra.uni WL_%=;\n"
        "WD_%=:\n\t}"
        :: "r"(mbar), "r"(parity) : "memory");
}

// ---------------- prep (gate-local permutation, R10) ----------------
// stored row n': jt=n'>>7, w=(n'>>4)&7, p=n'&15, e=p>>3, d=p&1, q=(p>>1)&3
//   -> original row (d+2e)*256 + jt*32 + w*4 + q
__global__ void prep_misc(const float* __restrict__ Wf, const float* __restrict__ Whf,
                          const float* __restrict__ bf, const float* __restrict__ Wb,
                          const float* __restrict__ Whb, const float* __restrict__ bb,
                          const float* __restrict__ Wo, const float* __restrict__ trans)
{
    int idx = blockIdx.x * blockDim.x + threadIdx.x;
    int stride = gridDim.x * blockDim.x;
    for (int i = idx; i < 2 * 1024 * 256; i += stride) {
        int dir = i >> 18;
        int r = (i >> 8) & 1023;
        int k = i & 255;
        int jt = r >> 7, w = (r >> 4) & 7, p = r & 15;
        int e = p >> 3, d = p & 1, q = (p >> 1) & 3;
        int pr = (d + 2 * e) * 256 + jt * 32 + w * 4 + q;
        const float* Wi = dir ? Wb : Wf;
        const float* Wh = dir ? Whb : Whf;
        g_wih[i] = __float2bfloat16(Wi[pr * 256 + k]);
        g_whh[i] = __float2bfloat16(Wh[pr * 256 + k]);
    }
    for (int i = idx; i < 32 * 512; i += stride) g_wo[i] = __float2bfloat16(Wo[i]);
    for (int i = idx; i < 2048; i += stride) {
        int dir = i >> 10;
        int r = i & 1023;
        int jt = r >> 7, w = (r >> 4) & 7, p = r & 15;
        int e = p >> 3, d = p & 1, q = (p >> 1) & 3;
        int pr = (d + 2 * e) * 256 + jt * 32 + w * 4 + q;
        g_bias[i] = (dir ? bb : bf)[pr];
    }
    for (int i = idx; i < 1024; i += stride) g_etrans[i] = __expf(trans[i]);
}

// ---------------- gather emb[sent] -> bf16 ----------------
__global__ void __launch_bounds__(256) gather_k(const float* __restrict__ emb,
                                                const int* __restrict__ sent)
{
    int m = blockIdx.x * 8 + (threadIdx.x >> 5);
    int lane = threadIdx.x & 31;
    int tok = sent[m];
    const float4* src = (const float4*)(emb + (size_t)tok * 256) + lane * 2;
    float4 a = src[0], b = src[1];
    uint4 v = make_uint4(packbf(a.x, a.y), packbf(a.z, a.w),
                         packbf(b.x, b.y), packbf(b.z, b.w));
    *(uint4*)(g_xemb + (size_t)m * 256 + lane * 8) = v;
}

// ---------------- input projection GEMM (legacy bf16 mma, R3-proven) ----------------
// g_x[dir][m][n'] = Xemb[m]·g_wih[dir][n'] + g_bias[dir][n']
#define PJS 72
__global__ void __launch_bounds__(256) proj_k()
{
    __shared__ __nv_bfloat16 sA[128 * PJS];
    __shared__ __nv_bfloat16 sB[128 * PJS];
    const int tx = threadIdx.x;
    const int w = tx >> 5, lane = tx & 31;
    const int nt = blockIdx.x, mt = blockIdx.y, dir = blockIdx.z;
    const size_t m0 = (size_t)mt * 128;
    const int n0 = nt * 128;
    const int moff = (w & 3) * 32, noff = (w >> 2) * 64;

    float acc[2][8][4];
#pragma unroll
    for (int a = 0; a < 2; a++)
#pragma unroll
        for (int b = 0; b < 8; b++)
#pragma unroll
            for (int c = 0; c < 4; c++) acc[a][b][c] = 0.0f;

    const int lrow = tx >> 3, lcol = (tx & 7) * 8;
    const __nv_bfloat16* gA = g_xemb + (m0 + lrow) * 256 + lcol;
    const __nv_bfloat16* gB = g_wih + ((size_t)dir * 1024 + n0 + lrow) * 256 + lcol;

    uint4 ra[4], rb[4];
#pragma unroll
    for (int s = 0; s < 4; s++) {
        ra[s] = *(const uint4*)(gA + s * 32 * 256);
        rb[s] = *(const uint4*)(gB + s * 32 * 256);
    }

    const unsigned aAddrBase = sptr(sA) + (((moff + (lane & 15)) * PJS + (lane >> 4) * 8) << 1);
    const int bg = lane >> 3;
    const unsigned bAddrBase = sptr(sB) + (((noff + (bg >> 1) * 8 + (lane & 7)) * PJS + (bg & 1) * 8) << 1);

    for (int kc = 0; kc < 4; kc++) {
        __syncthreads();
#pragma unroll
        for (int s = 0; s < 4; s++) {
            *(uint4*)&sA[(lrow + s * 32) * PJS + lcol] = ra[s];
            *(uint4*)&sB[(lrow + s * 32) * PJS + lcol] = rb[s];
        }
        __syncthreads();
        if (kc < 3) {
#pragma unroll
            for (int s = 0; s < 4; s++) {
                ra[s] = *(const uint4*)(gA + s * 32 * 256 + (kc + 1) * 64);
                rb[s] = *(const uint4*)(gB + s * 32 * 256 + (kc + 1) * 64);
            }
        }
#pragma unroll
        for (int kf = 0; kf < 4; kf++) {
            unsigned af[2][4];
            ldsm4(af[0], aAddrBase + kf * 32);
            ldsm4(af[1], aAddrBase + (16 * PJS * 2) + kf * 32);
#pragma unroll
            for (int p = 0; p < 4; p++) {
                unsigned b4[4];
                ldsm4(b4, bAddrBase + (p * 16 * PJS * 2) + kf * 32);
#pragma unroll
                for (int mf = 0; mf < 2; mf++) {
                    mma16816(acc[mf][2 * p + 0], af[mf], &b4[0]);
                    mma16816(acc[mf][2 * p + 1], af[mf], &b4[2]);
                }
            }
        }
    }

    __nv_bfloat16* outp = g_x + (size_t)dir * M_TOT * 1024;
#pragma unroll
    for (int nf = 0; nf < 8; nf++) {
        const int ncol = n0 + noff + nf * 8 + (lane & 3) * 2;
        const float b0v = g_bias[dir * 1024 + ncol];
        const float b1v = g_bias[dir * 1024 + ncol + 1];
#pragma unroll
        for (int mf = 0; mf < 2; mf++) {
            const size_t mlo = m0 + moff + mf * 16 + (lane >> 2);
            *(unsigned*)(outp + mlo * 1024 + ncol) =
                packbf(acc[mf][nf][0] + b0v, acc[mf][nf][1] + b1v);
            *(unsigned*)(outp + (mlo + 8) * 1024 + ncol) =
                packbf(acc[mf][nf][2] + b0v, acc[mf][nf][3] + b1v);
        }
    }
}

// ---------------- persistent bi-LSTM: cluster of 8, bulk DSMEM, x via LDG ----------------
__global__ void __launch_bounds__(256, 1) __cluster_dims__(8, 1, 1)
lstm_k(const float* __restrict__ h0, const float* __restrict__ c0)
{
    __shared__ __align__(16) __nv_bfloat16 sAB[2][4096];    // 2 x 8KB receive buffers
    __shared__ __align__(16) __nv_bfloat16 sStage[2][512];  // my 1KB block (for peers)
    __shared__ __align__(8) unsigned long long mbars[2];
    const int tx = threadIdx.x, w = tx >> 5, lane = tx & 31;
    const int bx = blockIdx.x;
    const int dir = bx >> 6, cid = bx & 63;
    const int b0 = (cid >> 3) << 4;
    const int jt = bx & 7;             // cluster rank
    const int N0 = jt << 7;
    const int j0 = jt << 5;

    // --- W_hh fragments in registers ---
    unsigned bw[16][2][2];
    {
        const int row = N0 + w * 16 + (lane >> 2);
        const __nv_bfloat16* baseH = g_whh + (size_t)dir * 1024 * 256;
#pragma unroll
        for (int kf = 0; kf < 16; kf++) {
#pragma unroll
            for (int nf = 0; nf < 2; nf++) {
                const size_t off = (size_t)(row + nf * 8) * 256 + kf * 16 + (lane & 3) * 2;
                bw[kf][nf][0] = *(const unsigned*)(baseH + off);
                bw[kf][nf][1] = *(const unsigned*)(baseH + off + 8);
            }
        }
    }

    const int r = lane >> 2;           // row 0..7 (and r+8)
    const int q = lane & 3;            // cell within warp group
    const int jc = w * 4 + q;          // cell 0..31 of this j-tile
    const int xcol = N0 + w * 16 + q * 2;

    float cs[2];
    cs[0] = c0[(size_t)(dir * 128 + b0 + r) * 256 + j0 + jc];
    cs[1] = c0[(size_t)(dir * 128 + b0 + r + 8) * 256 + j0 + jc];

    // --- mbarrier init + arm phase 0 ---
    if (tx == 0) {
#pragma unroll
        for (int i = 0; i < 2; i++) {
            unsigned mb = sptr(&mbars[i]);
            asm volatile("mbarrier.init.shared.b64 [%0], 1;" :: "r"(mb) : "memory");
            asm volatile("mbarrier.arrive.expect_tx.shared.b64 _, [%0], 7168;" :: "r"(mb) : "memory");
        }
    }

    // --- init sAB[0] from h0 (block k-major swizzled layout) ---
    for (int i = tx; i < 4096; i += 256) {
        const int k = i >> 4, m = i & 15;
        const int rank = k >> 5, kk = k & 31;
        const int eoff = rank * 512 + kk * 16 + (((m >> 3) ^ ((kk >> 2) & 1)) << 3) + (m & 7);
        sAB[0][eoff] = __float2bfloat16(h0[(size_t)(dir * 128 + b0 + m) * 256 + k]);
    }

    // --- peer addresses ---
    unsigned psa[8], pmb[8];
    {
        unsigned la = sptr(&sAB[0][0]);
        unsigned lm = sptr(&mbars[0]);
#pragma unroll
        for (int p = 0; p < 8; p++) {
            asm("mapa.shared::cluster.u32 %0, %1, %2;" : "=r"(psa[p]) : "r"(la), "r"(p));
            asm("mapa.shared::cluster.u32 %0, %1, %2;" : "=r"(pmb[p]) : "r"(lm), "r"(p));
        }
    }

    // --- ldmatrix.trans lane addressing for h blocks ---
    const int g = lane >> 3, lsub = lane & 7;
    const int kbase = lsub + ((g >> 1) << 3);
    const unsigned aoffH =
        (unsigned)(kbase * 32 + (((g & 1) ^ ((kbase >> 2) & 1)) << 4));
    const unsigned hBase = sptr(&sAB[0][0]);

    const __nv_bfloat16* xbase = g_x + (size_t)dir * M_TOT * 1024;

    // x prefetch for s=0
    unsigned xp[2][2];
    {
        const int t0 = dir ? 511 : 0;
#pragma unroll
        for (int nf = 0; nf < 2; nf++)
#pragma unroll
            for (int h2 = 0; h2 < 2; h2++)
                xp[nf][h2] = *(const unsigned*)(xbase +
                    (size_t)(t0 * 128 + b0 + r + h2 * 8) * 1024 + xcol + nf * 8);
    }
    __syncthreads();

    asm volatile("barrier.cluster.arrive.aligned;" ::: "memory");
    asm volatile("barrier.cluster.wait.aligned;" ::: "memory");

    int ph[2] = {0, 0};

    for (int s = 0; s < 512; s++) {
        const int t = dir ? (511 - s) : s;
        const int cur = s & 1, nxt = cur ^ 1;

        if (s > 0) {
            const unsigned mb = sptr(&mbars[cur]);
            mbar_wait(mb, ph[cur]);
            ph[cur] ^= 1;
            if (tx == 0 && s < 510)
                asm volatile("mbarrier.arrive.expect_tx.shared.b64 _, [%0], 7168;"
                             :: "r"(mb) : "memory");
        }

        // prefetch x(s+1) — overlaps h-mma
        unsigned xpn[2][2];
        if (s < 511) {
            const int tn = dir ? (510 - s) : (s + 1);
#pragma unroll
            for (int nf = 0; nf < 2; nf++)
#pragma unroll
                for (int h2 = 0; h2 < 2; h2++)
                    xpn[nf][h2] = *(const unsigned*)(xbase +
                        (size_t)(tn * 128 + b0 + r + h2 * 8) * 1024 + xcol + nf * 8);
        }

        // --- h-mma from sAB[cur] ---
        float acc0[2][4], acc1[2][4];
#pragma unroll
        for (int nf = 0; nf < 2; nf++)
#pragma unroll
            for (int i = 0; i < 4; i++) { acc0[nf][i] = 0.0f; acc1[nf][i] = 0.0f; }

        const unsigned hA = hBase + (unsigned)cur * 8192 + aoffH;
#pragma unroll
        for (int kf = 0; kf < 16; kf += 2) {
            unsigned af[4], af2[4];
            ldsm4t(af, hA + (kf >> 1) * 1024);
            mma16816(acc0[0], af, bw[kf][0]);
            mma16816(acc0[1], af, bw[kf][1]);
            ldsm4t(af2, hA + (kf >> 1) * 1024 + 512);
            mma16816(acc1[0], af2, bw[kf + 1][0]);
            mma16816(acc1[1], af2, bw[kf + 1][1]);
        }

        // --- gates: lane-local (i,f from nf=0 cols; g,o from nf=1 cols) ---
        float hv[2];
#pragma unroll
        for (int h2 = 0; h2 < 2; h2++) {
            float pi = acc0[0][h2 * 2 + 0] + acc1[0][h2 * 2 + 0] + lo16(xp[0][h2]);
            float pf = acc0[0][h2 * 2 + 1] + acc1[0][h2 * 2 + 1] + hi16(xp[0][h2]);
            float pg = acc0[1][h2 * 2 + 0] + acc1[1][h2 * 2 + 0] + lo16(xp[1][h2]);
            float po = acc0[1][h2 * 2 + 1] + acc1[1][h2 * 2 + 1] + hi16(xp[1][h2]);
            float ig = sigax(pi), fg = sigax(pf);
            float gg = tanha(pg), og = sigax(po);
            float c = fmaf(fg, cs[h2], ig * gg);
            cs[h2] = c;
            hv[h2] = og * tanha(c);
        }
#pragma unroll
        for (int nf = 0; nf < 2; nf++)
#pragma unroll
            for (int h2 = 0; h2 < 2; h2++) xp[nf][h2] = xpn[nf][h2];

        // --- stage into sStage[nxt] + own sAB[nxt] block ---
        if (s < 511) {
            __nv_bfloat16 b0v = __float2bfloat16_rn(hv[0]);
            __nv_bfloat16 b1v = __float2bfloat16_rn(hv[1]);
            const int e0 = jc * 16 + ((0 ^ ((jc >> 2) & 1)) << 3) + r;
            const int e1 = jc * 16 + ((1 ^ ((jc >> 2) & 1)) << 3) + r;
            sStage[nxt][e0] = b0v;
            sStage[nxt][e1] = b1v;
            sAB[nxt][jt * 512 + e0] = b0v;
            sAB[nxt][jt * 512 + e1] = b1v;
        }

        // --- g_h global write ---
        g_h[(size_t)(t * 128 + b0 + r) * 512 + dir * 256 + j0 + jc] = __float2bfloat16_rn(hv[0]);
        g_h[(size_t)(t * 128 + b0 + r + 8) * 512 + dir * 256 + j0 + jc] = __float2bfloat16_rn(hv[1]);

        __syncthreads();   // staging complete

        // --- elected thread: 7 bulk copies into peers' sAB[nxt] ---
        if (s < 511 && tx == 0) {
            asm volatile("fence.proxy.async.shared::cta;" ::: "memory");
            const unsigned src = sptr(&sStage[nxt][0]);
            const unsigned dstoff = (unsigned)(nxt * 8192 + jt * 1024);
            const unsigned mboff = (unsigned)(nxt * 8);
#pragma unroll
            for (int p = 0; p < 8; p++) {
                if (p == jt) continue;
                asm volatile(
                    "cp.async.bulk.shared::cluster.shared::cta.mbarrier::complete_tx::bytes "
                    "[%0], [%1], 1024, [%2];"
                    :: "r"(psa[p] + dstoff), "r"(src), "r"(pmb[p] + mboff) : "memory");
            }
        }
    }

    asm volatile("barrier.cluster.arrive.aligned;" ::: "memory");
    asm volatile("barrier.cluster.wait.aligned;" ::: "memory");
}

// ---------------- feats = g_h @ Wo^T + bo  (bf16 mma) ----------------
#define FAS 40
__global__ void __launch_bounds__(256) feats_k(const float* __restrict__ bo)
{
    __shared__ __nv_bfloat16 sB[32 * 520];
    __shared__ __nv_bfloat16 sA[128 * FAS];
    const int tx = threadIdx.x, w = tx >> 5, lane = tx & 31;
    const size_t m0 = (size_t)blockIdx.x * 128;
    const int moff = w * 16;

    for (int i = tx * 8; i < 16384; i += 2048) {
        int row = i >> 9, k = i & 511;
        *(uint4*)&sB[row * 520 + k] = *(const uint4*)&g_wo[i];
    }
    float acc[4][4];
#pragma unroll
    for (int a = 0; a < 4; a++)
#pragma unroll
        for (int b = 0; b < 4; b++) acc[a][b] = 0.0f;

    const int lrow = tx >> 2, lcol = (tx & 3) * 8;
    const __nv_bfloat16* gA = g_h + (m0 + lrow) * 512 + lcol;
    uint4 ra[2];
    ra[0] = *(const uint4*)(gA);
    ra[1] = *(const uint4*)(gA + 64 * 512);

    const unsigned aAddrBase = sptr(sA) + (((moff + (lane & 15)) * FAS + (lane >> 4) * 8) << 1);
    const int bg = lane >> 3;
    const unsigned bAddrBase = sptr(sB) + ((((bg >> 1) * 8 + (lane & 7)) * 520 + (bg & 1) * 8) << 1);

    for (int kc = 0; kc < 16; kc++) {
        __syncthreads();
        *(uint4*)&sA[lrow * FAS + lcol] = ra[0];
        *(uint4*)&sA[(lrow + 64) * FAS + lcol] = ra[1];
        __syncthreads();
        if (kc < 15) {
            ra[0] = *(const uint4*)(gA + (kc + 1) * 32);
            ra[1] = *(const uint4*)(gA + 64 * 512 + (kc + 1) * 32);
        }
#pragma unroll
        for (int kf = 0; kf < 2; kf++) {
            unsigned af[4];
            ldsm4(af, aAddrBase + kf * 32);
#pragma unroll
            for (int p = 0; p < 2; p++) {
                unsigned b4[4];
                ldsm4(b4, bAddrBase + (p * 16 * 520 * 2) + kc * 64 + kf * 32);
                mma16816(acc[2 * p + 0], af, &b4[0]);
                mma16816(acc[2 * p + 1], af, &b4[2]);
            }
        }
    }
#pragma unroll
    for (int nf = 0; nf < 4; nf++) {
        const int l = nf * 8 + (lane & 3) * 2;
        const float b0v = bo[l], b1v = bo[l + 1];
        const size_t mlo = m0 + moff + (lane >> 2);
        float2 v0 = make_float2(acc[nf][0] + b0v, acc[nf][1] + b1v);
        float2 v1 = make_float2(acc[nf][2] + b0v, acc[nf][3] + b1v);
        *(float2*)&g_feats[mlo * 32 + l] = v0;
        *(float2*)&g_feats[(mlo + 8) * 32 + l] = v1;
    }
}

// ---------------- CRF forward: linear-space, lane0-rescale, analytic first step ----------------
__global__ void __launch_bounds__(32) crf_fwd_kernel(const float* __restrict__ trans)
{
    const int b = blockIdx.x;
    const int l = threadIdx.x;
    float er[32];
#pragma unroll
    for (int i = 0; i < 32; i++) er[i] = g_etrans[i * 32 + l];

    float dp = trans[START_TAG * 32 + l] + g_feats[(size_t)(0 * 128 + b) * 32 + l];
    float sc_next = g_feats[(size_t)(1 * 128 + b) * 32 + l];

    for (int t = 1; t < 512; t++) {
        float sc = sc_next;
        if (t < 511) sc_next = g_feats[(size_t)((t + 1) * 128 + b) * 32 + l];
        float m = __shfl_sync(0xffffffffu, dp, 0);
        float u = __expf(dp - m);
        float a0 = 0.0f, a1 = 0.0f, a2 = 0.0f, a3 = 0.0f;
#pragma unroll
        for (int i = 0; i < 8; i++) {
            a0 = fmaf(__shfl_sync(0xffffffffu, u, i), er[i], a0);
            a1 = fmaf(__shfl_sync(0xffffffffu, u, i + 8), er[i + 8], a1);
            a2 = fmaf(__shfl_sync(0xffffffffu, u, i + 16), er[i + 16], a2);
            a3 = fmaf(__shfl_sync(0xffffffffu, u, i + 24), er[i + 24], a3);
        }
        dp = m + __logf((a0 + a1) + (a2 + a3)) + sc;
    }
    float m = dp;
#pragma unroll
    for (int o = 16; o; o >>= 1) m = fmaxf(m, __shfl_xor_sync(0xffffffffu, m, o));
    float e = __expf(dp - m);
#pragma unroll
    for (int o = 16; o; o >>= 1) e += __shfl_xor_sync(0xffffffffu, e, o);
    if (l == 0) g_Z[b] = m + __logf(e);
}

// ---------------- gold path score ----------------
__global__ void __launch_bounds__(256) gold_k(const int* __restrict__ labels,
                                              const float* __restrict__ trans)
{
    __shared__ float red[256];
    const int b = blockIdx.x, tx = threadIdx.x;
    float s = 0.0f;
    for (int t = tx; t < 512; t += 256) {
        int ln = labels[t * 128 + b];
        int lp = t ? labels[(t - 1) * 128 + b] : START_TAG;
        s += trans[lp * 32 + ln] + g_feats[(size_t)(t * 128 + b) * 32 + ln];
    }
    red[tx] = s;
    __syncthreads();
    for (int o = 128; o; o >>= 1) {
        if (tx < o) red[tx] += red[tx + o];
        __syncthreads();
    }
    if (tx == 0) g_gold[b] = red[0];
}

// ---------------- final reduce ----------------
__global__ void __launch_bounds__(128) final_kernel(float* __restrict__ out)
{
    __shared__ float red[128];
    const int b = threadIdx.x;
    red[b] = g_Z[b] - g_gold[b];
    __syncthreads();
    for (int o = 64; o; o >>= 1) {
        if (b < o) red[b] += red[b + o];
        __syncthreads();
    }
    if (b == 0) out[0] = red[0] / 128.0f;
}

// ---------------- launch ----------------
extern "C" void kernel_launch(void* const* d_in, const int* in_sizes, int n_in,
                              void* d_out, int out_size)
{
    (void)in_sizes; (void)n_in; (void)out_size;
    const float* emb    = (const float*)d_in[0];
    const float* W_ih_f = (const float*)d_in[1];
    const float* W_hh_f = (const float*)d_in[2];
    const float* b_f    = (const float*)d_in[3];
    const float* W_ih_b = (const float*)d_in[4];
    const float* W_hh_b = (const float*)d_in[5];
    const float* b_b    = (const float*)d_in[6];
    const float* Wo     = (const float*)d_in[7];
    const float* bo     = (const float*)d_in[8];
    const float* trans  = (const float*)d_in[9];
    const float* h0     = (const float*)d_in[10];
    const float* c0     = (const float*)d_in[11];
    const int*   sent   = (const int*)d_in[12];
    const int*   labels = (const int*)d_in[13];
    float* out = (float*)d_out;

    prep_misc<<<512, 256>>>(W_ih_f, W_hh_f, b_f, W_ih_b, W_hh_b, b_b, Wo, trans);
    gather_k<<<8192, 256>>>(emb, sent);
    proj_k<<<dim3(8, 512, 2), 256>>>();
    lstm_k<<<128, 256>>>(h0, c0);
    feats_k<<<512, 256>>>(bo);
    crf_fwd_kernel<<<128, 32>>>(trans);
    gold_k<<<128, 256>>>(labels, trans);
    final_kernel<<<1, 128>>>(out);
}